// round 7
// baseline (speedup 1.0000x reference)
#include <cuda_runtime.h>
#include <cuda_bf16.h>
#include <cstdint>

#define ODIM 1024
#define XSZ  4194304
#define WSZ  1048576
#define KOFF XSZ
#define VOFF (2*XSZ)
#define PPITCH 80           // proj smem pitch: 32 bf16 + 16B pad
#define APITCH 144          // attn smem pitch: 64 bf16 + 16B pad
// proj smem layout (per stage 40960B): A-hi, A-lo, B-hi, B-lo each 128*80=10240
#define PJ_SMEM 81920
// attn smem layout: K[st][p] at (st*2+p)*9216; V at 36864+(st*2+p)*9216; vm at 73728+st*256
#define AT_SMEM 74240

__device__ __align__(16) __nv_bfloat16 g_xh[3*XSZ], g_xl[3*XSZ];
__device__ __align__(16) __nv_bfloat16 g_wh[3*WSZ], g_wl[3*WSZ];
__device__ __align__(16) __nv_bfloat16 g_ph[3*XSZ], g_pl[3*XSZ];

// ---------------- helpers ----------------
__device__ __forceinline__ uint32_t smem_u32(const void* p) {
    uint32_t a;
    asm("{ .reg .u64 t; cvta.to.shared.u64 t, %1; cvt.u32.u64 %0, t; }" : "=r"(a) : "l"(p));
    return a;
}
__device__ __forceinline__ uint32_t packbf2(float e0, float e1) {  // e0 -> low half
    uint32_t r;
    asm("cvt.rn.bf16x2.f32 %0, %2, %1;" : "=r"(r) : "f"(e0), "f"(e1));
    return r;
}
__device__ __forceinline__ float bfhi(float x) { return __bfloat162float(__float2bfloat16(x)); }
__device__ __forceinline__ void ldsm4(uint32_t* r, uint32_t a) {
    asm volatile("ldmatrix.sync.aligned.m8n8.x4.shared.b16 {%0,%1,%2,%3}, [%4];"
                 : "=r"(r[0]), "=r"(r[1]), "=r"(r[2]), "=r"(r[3]) : "r"(a));
}
__device__ __forceinline__ void ldsm4t(uint32_t* r, uint32_t a) {
    asm volatile("ldmatrix.sync.aligned.m8n8.x4.trans.shared.b16 {%0,%1,%2,%3}, [%4];"
                 : "=r"(r[0]), "=r"(r[1]), "=r"(r[2]), "=r"(r[3]) : "r"(a));
}
__device__ __forceinline__ void mma_bf16(float* d, const uint32_t* a, uint32_t b0, uint32_t b1) {
    asm volatile("mma.sync.aligned.m16n8k16.row.col.f32.bf16.bf16.f32 "
                 "{%0,%1,%2,%3}, {%4,%5,%6,%7}, {%8,%9}, {%0,%1,%2,%3};"
                 : "+f"(d[0]), "+f"(d[1]), "+f"(d[2]), "+f"(d[3])
                 : "r"(a[0]), "r"(a[1]), "r"(a[2]), "r"(a[3]), "r"(b0), "r"(b1));
}
#define CPA16(dst, src) asm volatile("cp.async.cg.shared.global [%0], [%1], 16;" :: "r"(dst), "l"(src) : "memory")
#define CPC()   asm volatile("cp.async.commit_group;" ::: "memory")
#define CPW(n)  asm volatile("cp.async.wait_group %0;" :: "n"(n) : "memory")

// ---------------- split fp32 -> bf16 hi/lo (3 tensors per launch) ----------------
__global__ void split3(const float* __restrict__ s0, const float* __restrict__ s1,
                       const float* __restrict__ s2, __nv_bfloat16* __restrict__ h,
                       __nv_bfloat16* __restrict__ l, int n4each) {
    int i = blockIdx.x * blockDim.x + threadIdx.x;
    int a = i / n4each;
    if (a > 2) return;
    int j = i - a * n4each;
    const float* s = (a == 0) ? s0 : (a == 1) ? s1 : s2;
    float4 v = ((const float4*)s)[j];
    uint2 hh, ll;
    hh.x = packbf2(v.x, v.y);
    hh.y = packbf2(v.z, v.w);
    ll.x = packbf2(v.x - bfhi(v.x), v.y - bfhi(v.y));
    ll.y = packbf2(v.z - bfhi(v.z), v.w - bfhi(v.w));
    size_t o = (size_t)a * n4each + j;
    ((uint2*)h)[o] = hh;
    ((uint2*)l)[o] = ll;
}

// ---------------- projection: C[4096,1024]=X@W^T, tile 128x128, BK=32, 2-stage ----------------
__global__ __launch_bounds__(256) void proj_mma(
    const __nv_bfloat16* __restrict__ Ah_, const __nv_bfloat16* __restrict__ Al_,
    const __nv_bfloat16* __restrict__ Bh_, const __nv_bfloat16* __restrict__ Bl_,
    __nv_bfloat16* __restrict__ Ch, __nv_bfloat16* __restrict__ Cl)
{
    extern __shared__ __align__(16) char sm[];
    const int tid = threadIdx.x, wr = tid >> 5, lane = tid & 31;
    const int n0 = blockIdx.x * 128, m0 = blockIdx.y * 128;
    const int g = lane >> 2, t = lane & 3;
    const uint32_t sb = smem_u32(sm);
    const int wm = wr >> 1, wn = wr & 1;   // warp tile: rows wm*32.., cols wn*64..
    const uint32_t rB  = ((lane >> 4) & 1) * 8 + (lane & 7);
    const uint32_t cBo = ((lane >> 3) & 1) * 16;
    float acc[2][8][4] = {};

    auto issue = [&](int kt, int st) {
        const uint32_t base = sb + st * 40960;
        #pragma unroll
        for (int i = 0; i < 4; i++) {
            int idx = tid + 256 * i;       // 0..1023 over A-hi/A-lo
            int a = idx >> 9, r = (idx >> 2) & 127, gc = idx & 3;
            size_t go = (size_t)(m0 + r) * ODIM + kt * 32 + gc * 8;
            CPA16(base + a * 10240 + r * PPITCH + gc * 16, (a ? Al_ : Ah_) + go);
        }
        #pragma unroll
        for (int i = 0; i < 4; i++) {
            int idx = tid + 256 * i;       // B-hi/B-lo
            int a = idx >> 9, r = (idx >> 2) & 127, gc = idx & 3;
            size_t go = (size_t)(n0 + r) * ODIM + kt * 32 + gc * 8;
            CPA16(base + 20480 + a * 10240 + r * PPITCH + gc * 16, (a ? Bl_ : Bh_) + go);
        }
        CPC();
    };

    issue(0, 0);
    for (int kt = 0; kt < 32; kt++) {
        const int st = kt & 1;
        if (kt + 1 < 32) { issue(kt + 1, st ^ 1); CPW(1); } else { CPW(0); }
        __syncthreads();
        const uint32_t base = sb + st * 40960;
        #pragma unroll
        for (int kc = 0; kc < 2; kc++) {
            uint32_t ah[2][4], al[2][4];
            #pragma unroll
            for (int mi = 0; mi < 2; mi++) {
                uint32_t ao = base + (wm * 32 + mi * 16 + (lane & 15)) * PPITCH
                            + (lane >> 4) * 16 + kc * 32;
                ldsm4(ah[mi], ao);
                ldsm4(al[mi], ao + 10240);
            }
            #pragma unroll
            for (int nj = 0; nj < 4; nj++) {
                uint32_t bh[4], bl[4];
                uint32_t bo = base + 20480 + (wn * 64 + nj * 16 + rB) * PPITCH + cBo + kc * 32;
                ldsm4(bh, bo);
                ldsm4(bl, bo + 10240);
                #pragma unroll
                for (int mi = 0; mi < 2; mi++) {
                    mma_bf16(acc[mi][2*nj],   ah[mi], bh[0], bh[1]);
                    mma_bf16(acc[mi][2*nj+1], ah[mi], bh[2], bh[3]);
                    mma_bf16(acc[mi][2*nj],   ah[mi], bl[0], bl[1]);
                    mma_bf16(acc[mi][2*nj+1], ah[mi], bl[2], bl[3]);
                    mma_bf16(acc[mi][2*nj],   al[mi], bh[0], bh[1]);
                    mma_bf16(acc[mi][2*nj+1], al[mi], bh[2], bh[3]);
                }
            }
        }
        __syncthreads();
    }
    #pragma unroll
    for (int mi = 0; mi < 2; mi++) {
        const int r0 = m0 + wm * 32 + mi * 16 + g, r1 = r0 + 8;
        #pragma unroll
        for (int nj = 0; nj < 8; nj++) {
            int col = n0 + wn * 64 + nj * 8 + 2 * t;
            float c0 = acc[mi][nj][0], c1 = acc[mi][nj][1];
            float c2 = acc[mi][nj][2], c3 = acc[mi][nj][3];
            *(uint32_t*)(Ch + (size_t)r0 * ODIM + col) = packbf2(c0, c1);
            *(uint32_t*)(Ch + (size_t)r1 * ODIM + col) = packbf2(c2, c3);
            *(uint32_t*)(Cl + (size_t)r0 * ODIM + col) = packbf2(c0 - bfhi(c0), c1 - bfhi(c1));
            *(uint32_t*)(Cl + (size_t)r1 * ODIM + col) = packbf2(c2 - bfhi(c2), c3 - bfhi(c3));
        }
    }
}

// ---------------- attention: 128 q-rows/CTA, 64-key tiles, 2-stage cp.async ----------------
__global__ __launch_bounds__(256) void attn_mma(
    const float* __restrict__ v_mask, const float* __restrict__ q_mask,
    float* __restrict__ out,
    const __nv_bfloat16* __restrict__ Ph, const __nv_bfloat16* __restrict__ Pl)
{
    extern __shared__ __align__(16) char sm[];
    const int tid = threadIdx.x, wr = tid >> 5, lane = tid & 31;
    const int qt = blockIdx.x, h = blockIdx.y, b = blockIdx.z;
    const int q0 = qt * 128;
    const int g = lane >> 2, t = lane & 3;
    const uint32_t sb = smem_u32(sm);

    const __nv_bfloat16* Qh_b = Ph + (size_t)(b * 2048 + q0) * ODIM + h * 64;
    const __nv_bfloat16* Ql_b = Pl + (size_t)(b * 2048 + q0) * ODIM + h * 64;
    const __nv_bfloat16* Kh_b = Ph + KOFF + (size_t)(b * 2048) * ODIM + h * 64;
    const __nv_bfloat16* Kl_b = Pl + KOFF + (size_t)(b * 2048) * ODIM + h * 64;
    const __nv_bfloat16* Vh_b = Ph + VOFF + (size_t)(b * 2048) * ODIM + h * 64;
    const __nv_bfloat16* Vl_b = Pl + VOFF + (size_t)(b * 2048) * ODIM + h * 64;
    const float* vm = v_mask + (size_t)b * 2048;

    // ---- stage Q through K stage-0 buffers (two 64-row passes), grab fragments ----
    uint32_t qAh[4][4], qAl[4][4];
    #pragma unroll
    for (int p = 0; p < 2; p++) {
        if (p) __syncthreads();
        #pragma unroll
        for (int i = 0; i < 2; i++) {
            int idx = tid + 256 * i;       // 512 tasks = 64 rows x 8 chunks (both arrays per task)
            int r = (idx >> 3) & 63, gc = idx & 7;
            size_t go = (size_t)(p * 64 + r) * ODIM + gc * 8;
            uint32_t so = r * APITCH + gc * 16;
            *(uint4*)(sm + so)        = *(const uint4*)(Qh_b + go);
            *(uint4*)(sm + 9216 + so) = *(const uint4*)(Ql_b + go);
        }
        __syncthreads();
        if ((wr >> 2) == p) {
            const uint32_t aOff = sb + ((wr & 3) * 16 + (lane & 15)) * APITCH + (lane >> 4) * 16;
            #pragma unroll
            for (int kc = 0; kc < 4; kc++) {
                ldsm4(qAh[kc], aOff + kc * 32);
                ldsm4(qAl[kc], aOff + 9216 + kc * 32);
            }
        }
    }
    __syncthreads();

    float oacc[8][4] = {};
    float lr0 = 0.f, lr1 = 0.f;
    const int qrow0 = q0 + wr * 16 + g;
    const uint32_t rB  = ((lane >> 4) & 1) * 8 + (lane & 7);
    const uint32_t cBo = ((lane >> 3) & 1) * 16;

    auto issue = [&](int kt2, int st) {
        const int k0 = kt2 * 64;
        #pragma unroll
        for (int i = 0; i < 8; i++) {
            int idx = tid + 256 * i;       // 2048 tasks = 4 arrays x 64 rows x 8 chunks
            int arr = idx >> 9, r = (idx >> 3) & 63, gc = idx & 7;
            size_t go = (size_t)(k0 + r) * ODIM + gc * 8;
            const __nv_bfloat16* src = (arr == 0) ? Kh_b : (arr == 1) ? Kl_b
                                     : (arr == 2) ? Vh_b : Vl_b;
            uint32_t dst = (arr < 2)
                ? sb + (st * 2 + arr) * 9216 + r * APITCH + gc * 16
                : sb + 36864 + (st * 2 + (arr - 2)) * 9216 + r * APITCH + gc * 16;
            CPA16(dst, src + go);
        }
        if (tid < 16) CPA16(sb + 73728 + st * 256 + tid * 16, vm + k0 + tid * 4);
        CPC();
    };

    const int start = 2 * qt;
    issue(start, start & 1);
    for (int kt2 = start; kt2 < 32; kt2++) {
        const int st = kt2 & 1;
        const int k0 = kt2 * 64;
        if (kt2 + 1 < 32) { issue(kt2 + 1, st ^ 1); CPW(1); } else { CPW(0); }
        __syncthreads();
        const uint32_t bKh = sb + (st * 2 + 0) * 9216, bKl = sb + (st * 2 + 1) * 9216;
        const uint32_t bVh = sb + 36864 + (st * 2 + 0) * 9216, bVl = bVh + 9216;
        const float* svm = (const float*)(sm + 73728 + st * 256);

        #pragma unroll
        for (int jp = 0; jp < 4; jp++) {
            float s8[8] = {};
            #pragma unroll
            for (int kc = 0; kc < 4; kc++) {
                uint32_t bh[4], bl[4];
                uint32_t bo = (jp * 16 + rB) * APITCH + cBo + kc * 32;
                ldsm4(bh, bKh + bo);
                ldsm4(bl, bKl + bo);
                mma_bf16(s8 + 0, qAh[kc], bh[0], bh[1]);
                mma_bf16(s8 + 4, qAh[kc], bh[2], bh[3]);
                mma_bf16(s8 + 0, qAh[kc], bl[0], bl[1]);
                mma_bf16(s8 + 4, qAh[kc], bl[2], bl[3]);
                mma_bf16(s8 + 0, qAl[kc], bh[0], bh[1]);
                mma_bf16(s8 + 4, qAl[kc], bh[2], bh[3]);
            }
            float p[8];
            const int cb = jp * 16 + 2 * t;
            #pragma unroll
            for (int e = 0; e < 8; e++) {
                int tile = e >> 2, c = e & 3;
                int colL = cb + tile * 8 + (c & 1);
                int kg = k0 + colL;
                int qr = (c >= 2) ? qrow0 + 8 : qrow0;
                float vmv = svm[colL];
                p[e] = (kg <= qr || vmv == 0.f) ? 0.f : __expf(s8[e] * 0.125f);
            }
            lr0 += p[0] + p[1] + p[4] + p[5];
            lr1 += p[2] + p[3] + p[6] + p[7];
            uint32_t pah[4], pal[4];
            pah[0] = packbf2(p[0], p[1]);  pah[1] = packbf2(p[2], p[3]);
            pah[2] = packbf2(p[4], p[5]);  pah[3] = packbf2(p[6], p[7]);
            pal[0] = packbf2(p[0] - bfhi(p[0]), p[1] - bfhi(p[1]));
            pal[1] = packbf2(p[2] - bfhi(p[2]), p[3] - bfhi(p[3]));
            pal[2] = packbf2(p[4] - bfhi(p[4]), p[5] - bfhi(p[5]));
            pal[3] = packbf2(p[6] - bfhi(p[6]), p[7] - bfhi(p[7]));
            #pragma unroll
            for (int j2 = 0; j2 < 4; j2++) {
                uint32_t vh[4], vl[4];
                uint32_t vo = (jp * 16 + (lane & 15)) * APITCH + (j2 * 2 + (lane >> 4)) * 16;
                ldsm4t(vh, bVh + vo);
                ldsm4t(vl, bVl + vo);
                mma_bf16(oacc[2*j2],   pah, vh[0], vh[1]);
                mma_bf16(oacc[2*j2+1], pah, vh[2], vh[3]);
                mma_bf16(oacc[2*j2],   pah, vl[0], vl[1]);
                mma_bf16(oacc[2*j2+1], pah, vl[2], vl[3]);
                mma_bf16(oacc[2*j2],   pal, vh[0], vh[1]);
                mma_bf16(oacc[2*j2+1], pal, vh[2], vh[3]);
            }
        }
        __syncthreads();
    }

    // ---- epilogue ----
    lr0 += __shfl_xor_sync(0xffffffffu, lr0, 1);
    lr0 += __shfl_xor_sync(0xffffffffu, lr0, 2);
    lr1 += __shfl_xor_sync(0xffffffffu, lr1, 1);
    lr1 += __shfl_xor_sync(0xffffffffu, lr1, 2);
    const float qm0 = q_mask[(size_t)b * 2048 + qrow0];
    const float qm1 = q_mask[(size_t)b * 2048 + qrow0 + 8];
    const float inv0 = (lr0 > 0.f) ? qm0 / lr0 : 0.f;
    const float inv1 = (lr1 > 0.f) ? qm1 / lr1 : 0.f;
    float* o0 = out + (size_t)(b * 2048 + qrow0) * ODIM + h * 64;
    float* o1 = o0 + (size_t)8 * ODIM;
    #pragma unroll
    for (int j = 0; j < 8; j++) {
        *(float2*)(o0 + j * 8 + 2 * t) = make_float2(oacc[j][0] * inv0, oacc[j][1] * inv0);
        *(float2*)(o1 + j * 8 + 2 * t) = make_float2(oacc[j][2] * inv1, oacc[j][3] * inv1);
    }
}

// ---------------- degenerate rows (q >= last valid key): exact tie-average ----------------
__global__ void fallback_k(const float* __restrict__ v_mask, const float* __restrict__ q_mask,
                           float* __restrict__ out,
                           const __nv_bfloat16* __restrict__ Vh, const __nv_bfloat16* __restrict__ Vl)
{
    const int h = blockIdx.x, b = blockIdx.y, d = threadIdx.x;  // 64 threads
    __shared__ int s_kmax, s_cnt;
    const float* vm = v_mask + (size_t)b * 2048;
    if (d == 0) {
        int km = 0, c = 0;
        for (int k2 = 0; k2 < 2048; k2++) if (vm[k2] != 0.f) { km = k2; c++; }
        s_kmax = km; s_cnt = c;
    }
    const __nv_bfloat16* vh = Vh + (size_t)(b * 2048) * ODIM + h * 64 + d;
    const __nv_bfloat16* vl = Vl + (size_t)(b * 2048) * ODIM + h * 64 + d;
    float tm = 0.f;
    for (int k2 = 0; k2 < 2048; k2++)
        if (vm[k2] != 0.f)
            tm += __bfloat162float(vh[(size_t)k2 * ODIM]) + __bfloat162float(vl[(size_t)k2 * ODIM]);
    __syncthreads();
    const int kmax = s_kmax, cnt = s_cnt;
    float suf = 0.f;
    for (int k2 = 2047; k2 >= kmax; k2--) {
        const float qm = q_mask[(size_t)b * 2048 + k2];
        const int den = cnt + (2047 - k2);
        out[((size_t)(b * 2048 + k2)) * ODIM + h * 64 + d] =
            (den > 0) ? qm * (tm + suf) / (float)den : 0.f;
        suf += __bfloat162float(vh[(size_t)k2 * ODIM]) + __bfloat162float(vl[(size_t)k2 * ODIM]);
    }
}

// ---------------- launch ----------------
extern "C" void kernel_launch(void* const* d_in, const int* in_sizes, int n_in,
                              void* d_out, int out_size)
{
    const float* q     = (const float*)d_in[0];
    const float* k     = (const float*)d_in[1];
    const float* v     = (const float*)d_in[2];
    const float* vmask = (const float*)d_in[3];
    const float* qmask = (const float*)d_in[4];
    const float* Wq    = (const float*)d_in[5];
    const float* Wk    = (const float*)d_in[6];
    const float* Wv    = (const float*)d_in[7];
    float* out = (float*)d_out;

    __nv_bfloat16 *xh, *xl, *wh, *wl, *ph, *pl;
    cudaGetSymbolAddress((void**)&xh, g_xh);
    cudaGetSymbolAddress((void**)&xl, g_xl);
    cudaGetSymbolAddress((void**)&wh, g_wh);
    cudaGetSymbolAddress((void**)&wl, g_wl);
    cudaGetSymbolAddress((void**)&ph, g_ph);
    cudaGetSymbolAddress((void**)&pl, g_pl);

    cudaFuncSetAttribute(proj_mma, cudaFuncAttributeMaxDynamicSharedMemorySize, PJ_SMEM);
    cudaFuncSetAttribute(attn_mma, cudaFuncAttributeMaxDynamicSharedMemorySize, AT_SMEM);

    split3<<<12288, 256>>>(q, k, v, xh, xl, XSZ / 4);     // launch 0
    split3<<<3072, 256>>>(Wq, Wk, Wv, wh, wl, WSZ / 4);   // launch 1

    for (int s = 0; s < 3; s++)                           // launches 2,3,4
        proj_mma<<<dim3(8, 32), 256, PJ_SMEM>>>(
            xh + s * XSZ, xl + s * XSZ, wh + s * WSZ, wl + s * WSZ,
            ph + s * XSZ, pl + s * XSZ);

    attn_mma<<<dim3(16, 16, 2), 256, AT_SMEM>>>(vmask, qmask, out, ph, pl);  // launch 5
    fallback_k<<<dim3(16, 2), 64>>>(vmask, qmask, out, ph + 2*XSZ, pl + 2*XSZ);
}

// round 8
// speedup vs baseline: 1.9359x; 1.9359x over previous
#include <cuda_runtime.h>
#include <cuda_fp16.h>
#include <cstdint>

#define ODIM 1024
#define XSZ  4194304
#define WSZ  1048576
#define KOFF XSZ
#define VOFF (2*XSZ)
#define PPITCH 80           // proj smem pitch: 32 fp16 = 64B + 16B pad
#define APITCH 144          // attn smem pitch: 64 fp16 = 128B + 16B pad

__device__ __align__(16) __half g_x[3*XSZ];   // fp16 q,k,v inputs
__device__ __align__(16) __half g_w[3*WSZ];   // fp16 weights
__device__ __align__(16) __half g_p[3*XSZ];   // fp16 projections qw,kw,vw

// ---------------- helpers ----------------
__device__ __forceinline__ uint32_t smem_u32(const void* p) {
    uint32_t a;
    asm("{ .reg .u64 t; cvta.to.shared.u64 t, %1; cvt.u32.u64 %0, t; }" : "=r"(a) : "l"(p));
    return a;
}
__device__ __forceinline__ uint32_t packh2(float e0, float e1) {  // e0 -> low half
    __half2 h = __floats2half2_rn(e0, e1);
    return *reinterpret_cast<uint32_t*>(&h);
}
__device__ __forceinline__ void ldsm4(uint32_t* r, uint32_t a) {
    asm volatile("ldmatrix.sync.aligned.m8n8.x4.shared.b16 {%0,%1,%2,%3}, [%4];"
                 : "=r"(r[0]), "=r"(r[1]), "=r"(r[2]), "=r"(r[3]) : "r"(a));
}
__device__ __forceinline__ void ldsm4t(uint32_t* r, uint32_t a) {
    asm volatile("ldmatrix.sync.aligned.m8n8.x4.trans.shared.b16 {%0,%1,%2,%3}, [%4];"
                 : "=r"(r[0]), "=r"(r[1]), "=r"(r[2]), "=r"(r[3]) : "r"(a));
}
__device__ __forceinline__ void mma_f16(float* d, const uint32_t* a, uint32_t b0, uint32_t b1) {
    asm volatile("mma.sync.aligned.m16n8k16.row.col.f32.f16.f16.f32 "
                 "{%0,%1,%2,%3}, {%4,%5,%6,%7}, {%8,%9}, {%0,%1,%2,%3};"
                 : "+f"(d[0]), "+f"(d[1]), "+f"(d[2]), "+f"(d[3])
                 : "r"(a[0]), "r"(a[1]), "r"(a[2]), "r"(a[3]), "r"(b0), "r"(b1));
}
#define CPA16(dst, src) asm volatile("cp.async.cg.shared.global [%0], [%1], 16;" :: "r"(dst), "l"(src) : "memory")
#define CPC()   asm volatile("cp.async.commit_group;" ::: "memory")
#define CPW(n)  asm volatile("cp.async.wait_group %0;" :: "n"(n) : "memory")

// ---------------- convert fp32 -> fp16 (3 tensors per launch) ----------------
__global__ void conv3(const float* __restrict__ s0, const float* __restrict__ s1,
                      const float* __restrict__ s2, __half* __restrict__ h, int n4each) {
    int i = blockIdx.x * blockDim.x + threadIdx.x;
    int a = i / n4each;
    if (a > 2) return;
    int j = i - a * n4each;
    const float* s = (a == 0) ? s0 : (a == 1) ? s1 : s2;
    float4 v = ((const float4*)s)[j];
    uint2 hh;
    hh.x = packh2(v.x, v.y);
    hh.y = packh2(v.z, v.w);
    ((uint2*)h)[(size_t)a * n4each + j] = hh;
}

// ---------------- projection: C[4096,1024]=X@W^T, tile 128x128, BK=32, 2-stage ----------------
__global__ __launch_bounds__(256) void proj_mma(
    const __half* __restrict__ A_, const __half* __restrict__ B_,
    __half* __restrict__ C_)
{
    __shared__ __align__(16) char sA[2][128*PPITCH];
    __shared__ __align__(16) char sB[2][128*PPITCH];
    const int tid = threadIdx.x, wr = tid >> 5, lane = tid & 31;
    const int n0 = blockIdx.x * 128, m0 = blockIdx.y * 128;
    const int g = lane >> 2, t = lane & 3;
    const int wm = wr >> 1, wn = wr & 1;   // warp tile: rows wm*32.., cols wn*64..
    uint32_t bA[2], bB[2];
    bA[0] = smem_u32(sA[0]); bA[1] = smem_u32(sA[1]);
    bB[0] = smem_u32(sB[0]); bB[1] = smem_u32(sB[1]);
    const uint32_t rB  = ((lane >> 4) & 1) * 8 + (lane & 7);
    const uint32_t cBo = ((lane >> 3) & 1) * 16;
    float acc[2][8][4] = {};

    auto issue = [&](int kt, int st) {
        #pragma unroll
        for (int i = 0; i < 4; i++) {
            int idx = tid + 256 * i;       // 1024 tasks = 2 arrays x 128 rows x 4 chunks
            int arr = idx >> 9, r = (idx >> 2) & 127, gc = idx & 3;
            size_t go = (size_t)((arr ? n0 : m0) + r) * ODIM + kt * 32 + gc * 8;
            uint32_t dst = (arr ? bB[st] : bA[st]) + r * PPITCH + gc * 16;
            CPA16(dst, (arr ? B_ : A_) + go);
        }
        CPC();
    };

    issue(0, 0);
    for (int kt = 0; kt < 32; kt++) {
        const int st = kt & 1;
        if (kt + 1 < 32) { issue(kt + 1, st ^ 1); CPW(1); } else { CPW(0); }
        __syncthreads();
        #pragma unroll
        for (int kc = 0; kc < 2; kc++) {
            uint32_t ah[2][4];
            #pragma unroll
            for (int mi = 0; mi < 2; mi++)
                ldsm4(ah[mi], bA[st] + (wm * 32 + mi * 16 + (lane & 15)) * PPITCH
                              + (lane >> 4) * 16 + kc * 32);
            #pragma unroll
            for (int nj = 0; nj < 4; nj++) {
                uint32_t bh[4];
                ldsm4(bh, bB[st] + (wn * 64 + nj * 16 + rB) * PPITCH + cBo + kc * 32);
                #pragma unroll
                for (int mi = 0; mi < 2; mi++) {
                    mma_f16(acc[mi][2*nj],   ah[mi], bh[0], bh[1]);
                    mma_f16(acc[mi][2*nj+1], ah[mi], bh[2], bh[3]);
                }
            }
        }
        __syncthreads();
    }
    #pragma unroll
    for (int mi = 0; mi < 2; mi++) {
        const int r0 = m0 + wm * 32 + mi * 16 + g, r1 = r0 + 8;
        #pragma unroll
        for (int nj = 0; nj < 8; nj++) {
            int col = n0 + wn * 64 + nj * 8 + 2 * t;
            *(uint32_t*)(C_ + (size_t)r0 * ODIM + col) = packh2(acc[mi][nj][0], acc[mi][nj][1]);
            *(uint32_t*)(C_ + (size_t)r1 * ODIM + col) = packh2(acc[mi][nj][2], acc[mi][nj][3]);
        }
    }
}

// ---------------- attention: 128 q-rows/CTA, 64-key tiles, 2-stage, causal skip ----------------
__global__ __launch_bounds__(256) void attn_mma(
    const float* __restrict__ v_mask, const float* __restrict__ q_mask,
    float* __restrict__ out, const __half* __restrict__ P_)
{
    __shared__ __align__(16) char sK[2][64*APITCH];
    __shared__ __align__(16) char sV[2][64*APITCH];
    __shared__ __align__(16) float svm[2][64];
    const int tid = threadIdx.x, wr = tid >> 5, lane = tid & 31;
    const int qt = blockIdx.x, h = blockIdx.y, b = blockIdx.z;
    const int q0 = qt * 128;
    const int g = lane >> 2, t = lane & 3;
    uint32_t bK[2], bV[2], bvm[2];
    bK[0] = smem_u32(sK[0]); bK[1] = smem_u32(sK[1]);
    bV[0] = smem_u32(sV[0]); bV[1] = smem_u32(sV[1]);
    bvm[0] = smem_u32(svm[0]); bvm[1] = smem_u32(svm[1]);

    const __half* Q_b = P_ + (size_t)(b * 2048 + q0) * ODIM + h * 64;
    const __half* K_b = P_ + KOFF + (size_t)(b * 2048) * ODIM + h * 64;
    const __half* V_b = P_ + VOFF + (size_t)(b * 2048) * ODIM + h * 64;
    const float* vm = v_mask + (size_t)b * 2048;

    // ---- stage Q through sK[0] (two 64-row passes), grab fragments ----
    uint32_t qA[4][4];
    #pragma unroll
    for (int p = 0; p < 2; p++) {
        if (p) __syncthreads();
        #pragma unroll
        for (int i = 0; i < 2; i++) {
            int idx = tid + 256 * i;       // 512 tasks = 64 rows x 8 chunks
            int r = (idx >> 3) & 63, gc = idx & 7;
            *(uint4*)(sK[0] + r * APITCH + gc * 16) =
                *(const uint4*)(Q_b + (size_t)(p * 64 + r) * ODIM + gc * 8);
        }
        __syncthreads();
        if ((wr >> 2) == p) {
            const uint32_t aOff = bK[0] + ((wr & 3) * 16 + (lane & 15)) * APITCH + (lane >> 4) * 16;
            #pragma unroll
            for (int kc = 0; kc < 4; kc++) ldsm4(qA[kc], aOff + kc * 32);
        }
    }
    __syncthreads();

    float oacc[8][4] = {};
    float lr0 = 0.f, lr1 = 0.f;
    const int qrow0 = q0 + wr * 16 + g;
    const uint32_t rB  = ((lane >> 4) & 1) * 8 + (lane & 7);
    const uint32_t cBo = ((lane >> 3) & 1) * 16;

    auto issue = [&](int kt2, int st) {
        const int k0 = kt2 * 64;
        #pragma unroll
        for (int i = 0; i < 4; i++) {
            int idx = tid + 256 * i;       // 1024 tasks = 2 arrays x 64 rows x 8 chunks
            int arr = idx >> 9, r = (idx >> 3) & 63, gc = idx & 7;
            size_t go = (size_t)(k0 + r) * ODIM + gc * 8;
            uint32_t dst = (arr ? bV[st] : bK[st]) + r * APITCH + gc * 16;
            CPA16(dst, (arr ? V_b : K_b) + go);
        }
        if (tid < 16) CPA16(bvm[st] + tid * 16, vm + k0 + tid * 4);
        CPC();
    };

    const int start = 2 * qt;
    issue(start, start & 1);
    for (int kt2 = start; kt2 < 32; kt2++) {
        const int st = kt2 & 1;
        const int k0 = kt2 * 64;
        if (kt2 + 1 < 32) { issue(kt2 + 1, st ^ 1); CPW(1); } else { CPW(0); }
        __syncthreads();

        #pragma unroll
        for (int jp = 0; jp < 4; jp++) {
            float s8[8] = {};
            #pragma unroll
            for (int kc = 0; kc < 4; kc++) {
                uint32_t bh[4];
                ldsm4(bh, bK[st] + (jp * 16 + rB) * APITCH + cBo + kc * 32);
                mma_f16(s8 + 0, qA[kc], bh[0], bh[1]);
                mma_f16(s8 + 4, qA[kc], bh[2], bh[3]);
            }
            float p[8];
            const int cb = jp * 16 + 2 * t;
            #pragma unroll
            for (int e = 0; e < 8; e++) {
                int tile = e >> 2, c = e & 3;
                int colL = cb + tile * 8 + (c & 1);
                int kg = k0 + colL;
                int qr = (c >= 2) ? qrow0 + 8 : qrow0;
                float vmv = svm[st][colL];
                p[e] = (kg <= qr || vmv == 0.f) ? 0.f : __expf(s8[e] * 0.125f);
            }
            lr0 += p[0] + p[1] + p[4] + p[5];
            lr1 += p[2] + p[3] + p[6] + p[7];
            uint32_t pa[4];
            pa[0] = packh2(p[0], p[1]);  pa[1] = packh2(p[2], p[3]);
            pa[2] = packh2(p[4], p[5]);  pa[3] = packh2(p[6], p[7]);
            #pragma unroll
            for (int j2 = 0; j2 < 4; j2++) {
                uint32_t vh[4];
                ldsm4t(vh, bV[st] + (jp * 16 + (lane & 15)) * APITCH + (j2 * 2 + (lane >> 4)) * 16);
                mma_f16(oacc[2*j2],   pa, vh[0], vh[1]);
                mma_f16(oacc[2*j2+1], pa, vh[2], vh[3]);
            }
        }
        __syncthreads();
    }

    // ---- epilogue ----
    lr0 += __shfl_xor_sync(0xffffffffu, lr0, 1);
    lr0 += __shfl_xor_sync(0xffffffffu, lr0, 2);
    lr1 += __shfl_xor_sync(0xffffffffu, lr1, 1);
    lr1 += __shfl_xor_sync(0xffffffffu, lr1, 2);
    const float qm0 = q_mask[(size_t)b * 2048 + qrow0];
    const float qm1 = q_mask[(size_t)b * 2048 + qrow0 + 8];
    const float inv0 = (lr0 > 0.f) ? qm0 / lr0 : 0.f;
    const float inv1 = (lr1 > 0.f) ? qm1 / lr1 : 0.f;
    float* o0 = out + (size_t)(b * 2048 + qrow0) * ODIM + h * 64;
    float* o1 = o0 + (size_t)8 * ODIM;
    #pragma unroll
    for (int j = 0; j < 8; j++) {
        *(float2*)(o0 + j * 8 + 2 * t) = make_float2(oacc[j][0] * inv0, oacc[j][1] * inv0);
        *(float2*)(o1 + j * 8 + 2 * t) = make_float2(oacc[j][2] * inv1, oacc[j][3] * inv1);
    }
}

// ---------------- degenerate rows (q >= last valid key): exact tie-average ----------------
__global__ void fallback_k(const float* __restrict__ v_mask, const float* __restrict__ q_mask,
                           float* __restrict__ out, const __half* __restrict__ Vw)
{
    const int h = blockIdx.x, b = blockIdx.y, d = threadIdx.x;  // 64 threads
    __shared__ int s_kmax, s_cnt;
    const float* vm = v_mask + (size_t)b * 2048;
    if (d == 0) {
        int km = 0, c = 0;
        for (int k2 = 0; k2 < 2048; k2++) if (vm[k2] != 0.f) { km = k2; c++; }
        s_kmax = km; s_cnt = c;
    }
    const __half* vh = Vw + (size_t)(b * 2048) * ODIM + h * 64 + d;
    float tm = 0.f;
    for (int k2 = 0; k2 < 2048; k2++)
        if (vm[k2] != 0.f) tm += __half2float(vh[(size_t)k2 * ODIM]);
    __syncthreads();
    const int kmax = s_kmax, cnt = s_cnt;
    float suf = 0.f;
    for (int k2 = 2047; k2 >= kmax; k2--) {
        const float qm = q_mask[(size_t)b * 2048 + k2];
        const int den = cnt + (2047 - k2);
        out[((size_t)(b * 2048 + k2)) * ODIM + h * 64 + d] =
            (den > 0) ? qm * (tm + suf) / (float)den : 0.f;
        suf += __half2float(vh[(size_t)k2 * ODIM]);
    }
}

// ---------------- launch ----------------
extern "C" void kernel_launch(void* const* d_in, const int* in_sizes, int n_in,
                              void* d_out, int out_size)
{
    const float* q     = (const float*)d_in[0];
    const float* k     = (const float*)d_in[1];
    const float* v     = (const float*)d_in[2];
    const float* vmask = (const float*)d_in[3];
    const float* qmask = (const float*)d_in[4];
    const float* Wq    = (const float*)d_in[5];
    const float* Wk    = (const float*)d_in[6];
    const float* Wv    = (const float*)d_in[7];
    float* out = (float*)d_out;

    __half *x16, *w16, *p16;
    cudaGetSymbolAddress((void**)&x16, g_x);
    cudaGetSymbolAddress((void**)&w16, g_w);
    cudaGetSymbolAddress((void**)&p16, g_p);

    conv3<<<12288, 256>>>(q, k, v, x16, XSZ / 4);         // launch 0
    conv3<<<3072, 256>>>(Wq, Wk, Wv, w16, WSZ / 4);       // launch 1

    for (int s = 0; s < 3; s++)                           // launches 2,3,4
        proj_mma<<<dim3(8, 32), 256>>>(x16 + s * XSZ, w16 + s * WSZ, p16 + s * XSZ);

    attn_mma<<<dim3(16, 16, 2), 256>>>(vmask, qmask, out, p16);   // launch 5
    fallback_k<<<dim3(16, 2), 64>>>(vmask, qmask, out, p16 + 2*XSZ);
}

// round 9
// speedup vs baseline: 2.0643x; 1.0663x over previous
#include <cuda_runtime.h>
#include <cuda_fp16.h>
#include <cstdint>

#define ODIM 1024
#define XSZ  4194304
#define WSZ  1048576
#define KOFF XSZ
#define VOFF (2*XSZ)
#define PPITCH 80           // proj smem pitch: 32 fp16 = 64B + 16B pad
#define APITCH 144          // attn smem pitch: 64 fp16 = 128B + 16B pad
#define PJ_SMEM 61440       // 3 stages x (A 10240 + B 10240)
#define AT_STG  18432       // attn per-stage: K 9216 + V 9216
#define AT_SMEM 56320       // 3*18432 + vm 3*256 + pad

__device__ __align__(16) __half g_x[3*XSZ];   // fp16 q,k,v inputs
__device__ __align__(16) __half g_w[3*WSZ];   // fp16 weights
__device__ __align__(16) __half g_p[3*XSZ];   // fp16 projections qw,kw,vw

// ---------------- helpers ----------------
__device__ __forceinline__ uint32_t smem_u32(const void* p) {
    uint32_t a;
    asm("{ .reg .u64 t; cvta.to.shared.u64 t, %1; cvt.u32.u64 %0, t; }" : "=r"(a) : "l"(p));
    return a;
}
__device__ __forceinline__ uint32_t packh2(float e0, float e1) {  // e0 -> low half
    __half2 h = __floats2half2_rn(e0, e1);
    return *reinterpret_cast<uint32_t*>(&h);
}
__device__ __forceinline__ void ldsm4(uint32_t* r, uint32_t a) {
    asm volatile("ldmatrix.sync.aligned.m8n8.x4.shared.b16 {%0,%1,%2,%3}, [%4];"
                 : "=r"(r[0]), "=r"(r[1]), "=r"(r[2]), "=r"(r[3]) : "r"(a));
}
__device__ __forceinline__ void ldsm4t(uint32_t* r, uint32_t a) {
    asm volatile("ldmatrix.sync.aligned.m8n8.x4.trans.shared.b16 {%0,%1,%2,%3}, [%4];"
                 : "=r"(r[0]), "=r"(r[1]), "=r"(r[2]), "=r"(r[3]) : "r"(a));
}
__device__ __forceinline__ void mma_f16(float* d, const uint32_t* a, uint32_t b0, uint32_t b1) {
    asm volatile("mma.sync.aligned.m16n8k16.row.col.f32.f16.f16.f32 "
                 "{%0,%1,%2,%3}, {%4,%5,%6,%7}, {%8,%9}, {%0,%1,%2,%3};"
                 : "+f"(d[0]), "+f"(d[1]), "+f"(d[2]), "+f"(d[3])
                 : "r"(a[0]), "r"(a[1]), "r"(a[2]), "r"(a[3]), "r"(b0), "r"(b1));
}
#define CPA16(dst, src) asm volatile("cp.async.cg.shared.global [%0], [%1], 16;" :: "r"(dst), "l"(src) : "memory")
#define CPC()   asm volatile("cp.async.commit_group;" ::: "memory")
#define CPW(n)  asm volatile("cp.async.wait_group %0;" :: "n"(n) : "memory")

// ---------------- convert fp32 -> fp16 (3 tensors per launch) ----------------
__global__ void conv3(const float* __restrict__ s0, const float* __restrict__ s1,
                      const float* __restrict__ s2, __half* __restrict__ h, int n4each) {
    int i = blockIdx.x * blockDim.x + threadIdx.x;
    int a = i / n4each;
    if (a > 2) return;
    int j = i - a * n4each;
    const float* s = (a == 0) ? s0 : (a == 1) ? s1 : s2;
    float4 v = ((const float4*)s)[j];
    uint2 hh;
    hh.x = packh2(v.x, v.y);
    hh.y = packh2(v.z, v.w);
    ((uint2*)h)[(size_t)a * n4each + j] = hh;
}

// ---------------- projection (all 3 fused via grid.z): C=X@W^T, tile 128x128, BK=32, 3-stage ----------------
__global__ __launch_bounds__(256) void proj_mma(
    const __half* __restrict__ X_, const __half* __restrict__ W_, __half* __restrict__ P_)
{
    extern __shared__ __align__(16) char sm[];
    const uint32_t sb = smem_u32(sm);
    const int z = blockIdx.z;
    const __half* A_ = X_ + (size_t)z * XSZ;
    const __half* B_ = W_ + (size_t)z * WSZ;
    __half* C_ = P_ + (size_t)z * XSZ;
    const int tid = threadIdx.x, wr = tid >> 5, lane = tid & 31;
    const int n0 = blockIdx.x * 128, m0 = blockIdx.y * 128;
    const int g = lane >> 2, t = lane & 3;
    const int wm = wr >> 1, wn = wr & 1;
    const uint32_t rB  = ((lane >> 4) & 1) * 8 + (lane & 7);
    const uint32_t cBo = ((lane >> 3) & 1) * 16;
    float acc[2][8][4] = {};

    auto issue = [&](int kt) {
        if (kt < 32) {
            const uint32_t base = sb + (uint32_t)(kt % 3) * 20480;
            #pragma unroll
            for (int i = 0; i < 4; i++) {
                int idx = tid + 256 * i;      // 1024 = 2 arrays x 128 rows x 4 chunks
                int arr = idx >> 9, r = (idx >> 2) & 127, gc = idx & 3;
                size_t go = (size_t)((arr ? n0 : m0) + r) * ODIM + kt * 32 + gc * 8;
                CPA16(base + arr * 10240 + r * PPITCH + gc * 16, (arr ? B_ : A_) + go);
            }
        }
        CPC();
    };

    issue(0); issue(1);
    for (int kt = 0; kt < 32; kt++) {
        CPW(1);
        __syncthreads();
        issue(kt + 2);
        const uint32_t base = sb + (uint32_t)(kt % 3) * 20480;
        #pragma unroll
        for (int kc = 0; kc < 2; kc++) {
            uint32_t ah[2][4];
            #pragma unroll
            for (int mi = 0; mi < 2; mi++)
                ldsm4(ah[mi], base + (wm * 32 + mi * 16 + (lane & 15)) * PPITCH
                              + (lane >> 4) * 16 + kc * 32);
            #pragma unroll
            for (int nj = 0; nj < 4; nj++) {
                uint32_t bh[4];
                ldsm4(bh, base + 10240 + (wn * 64 + nj * 16 + rB) * PPITCH + cBo + kc * 32);
                #pragma unroll
                for (int mi = 0; mi < 2; mi++) {
                    mma_f16(acc[mi][2*nj],   ah[mi], bh[0], bh[1]);
                    mma_f16(acc[mi][2*nj+1], ah[mi], bh[2], bh[3]);
                }
            }
        }
    }
    #pragma unroll
    for (int mi = 0; mi < 2; mi++) {
        const int r0 = m0 + wm * 32 + mi * 16 + g, r1 = r0 + 8;
        #pragma unroll
        for (int nj = 0; nj < 8; nj++) {
            int col = n0 + wn * 64 + nj * 8 + 2 * t;
            *(uint32_t*)(C_ + (size_t)r0 * ODIM + col) = packh2(acc[mi][nj][0], acc[mi][nj][1]);
            *(uint32_t*)(C_ + (size_t)r1 * ODIM + col) = packh2(acc[mi][nj][2], acc[mi][nj][3]);
        }
    }
}

// ---------------- attention: 128 q-rows/CTA, 64-key tiles, 3-stage, causal skip ----------------
__global__ __launch_bounds__(256) void attn_mma(
    const float* __restrict__ v_mask, const float* __restrict__ q_mask,
    float* __restrict__ out, const __half* __restrict__ P_)
{
    extern __shared__ __align__(16) char sm[];
    const uint32_t sb = smem_u32(sm);
    const int tid = threadIdx.x, wr = tid >> 5, lane = tid & 31;
    const int qt = blockIdx.x, h = blockIdx.y, b = blockIdx.z;
    const int q0 = qt * 128;
    const int g = lane >> 2, t = lane & 3;

    const __half* Q_b = P_ + (size_t)(b * 2048 + q0) * ODIM + h * 64;
    const __half* K_b = P_ + KOFF + (size_t)(b * 2048) * ODIM + h * 64;
    const __half* V_b = P_ + VOFF + (size_t)(b * 2048) * ODIM + h * 64;
    const float* vm = v_mask + (size_t)b * 2048;

    // ---- stage Q through stage-0 K area (two 64-row passes), grab fragments ----
    uint32_t qA[4][4];
    #pragma unroll
    for (int p = 0; p < 2; p++) {
        if (p) __syncthreads();
        #pragma unroll
        for (int i = 0; i < 2; i++) {
            int idx = tid + 256 * i;          // 512 = 64 rows x 8 chunks
            int r = (idx >> 3) & 63, gc = idx & 7;
            *(uint4*)(sm + r * APITCH + gc * 16) =
                *(const uint4*)(Q_b + (size_t)(p * 64 + r) * ODIM + gc * 8);
        }
        __syncthreads();
        if ((wr >> 2) == p) {
            const uint32_t aOff = sb + ((wr & 3) * 16 + (lane & 15)) * APITCH + (lane >> 4) * 16;
            #pragma unroll
            for (int kc = 0; kc < 4; kc++) ldsm4(qA[kc], aOff + kc * 32);
        }
    }
    __syncthreads();

    float oacc[8][4] = {};
    float lr0 = 0.f, lr1 = 0.f;
    const int qrow0 = q0 + wr * 16 + g;
    const uint32_t rB  = ((lane >> 4) & 1) * 8 + (lane & 7);
    const uint32_t cBo = ((lane >> 3) & 1) * 16;

    auto issue = [&](int kt2) {
        if (kt2 < 32) {
            const int st = kt2 % 3;
            const int k0 = kt2 * 64;
            const uint32_t bKs = sb + (uint32_t)st * AT_STG;
            #pragma unroll
            for (int i = 0; i < 4; i++) {
                int idx = tid + 256 * i;      // 1024 = 2 arrays x 64 rows x 8 chunks
                int arr = idx >> 9, r = (idx >> 3) & 63, gc = idx & 7;
                size_t go = (size_t)(k0 + r) * ODIM + gc * 8;
                CPA16(bKs + arr * 9216 + r * APITCH + gc * 16, (arr ? V_b : K_b) + go);
            }
            if (tid < 16) CPA16(sb + 3 * AT_STG + st * 256 + tid * 16, vm + k0 + tid * 4);
        }
        CPC();
    };

    const int start = 2 * qt;
    issue(start); issue(start + 1);
    for (int kt2 = start; kt2 < 32; kt2++) {
        const int st = kt2 % 3;
        const int k0 = kt2 * 64;
        CPW(1);
        __syncthreads();
        issue(kt2 + 2);
        const uint32_t bKs = sb + (uint32_t)st * AT_STG;
        const uint32_t bVs = bKs + 9216;
        const float* svm = (const float*)(sm + 3 * AT_STG + st * 256);

        #pragma unroll
        for (int jp = 0; jp < 4; jp++) {
            float s8[8] = {};
            #pragma unroll
            for (int kc = 0; kc < 4; kc++) {
                uint32_t bh[4];
                ldsm4(bh, bKs + (jp * 16 + rB) * APITCH + cBo + kc * 32);
                mma_f16(s8 + 0, qA[kc], bh[0], bh[1]);
                mma_f16(s8 + 4, qA[kc], bh[2], bh[3]);
            }
            float p[8];
            const int cb = jp * 16 + 2 * t;
            #pragma unroll
            for (int e = 0; e < 8; e++) {
                int tile = e >> 2, c = e & 3;
                int colL = cb + tile * 8 + (c & 1);
                int kg = k0 + colL;
                int qr = (c >= 2) ? qrow0 + 8 : qrow0;
                float vmv = svm[colL];
                p[e] = (kg <= qr || vmv == 0.f) ? 0.f : __expf(s8[e] * 0.125f);
            }
            lr0 += p[0] + p[1] + p[4] + p[5];
            lr1 += p[2] + p[3] + p[6] + p[7];
            uint32_t pa[4];
            pa[0] = packh2(p[0], p[1]);  pa[1] = packh2(p[2], p[3]);
            pa[2] = packh2(p[4], p[5]);  pa[3] = packh2(p[6], p[7]);
            #pragma unroll
            for (int j2 = 0; j2 < 4; j2++) {
                uint32_t vh[4];
                ldsm4t(vh, bVs + (jp * 16 + (lane & 15)) * APITCH + (j2 * 2 + (lane >> 4)) * 16);
                mma_f16(oacc[2*j2],   pa, vh[0], vh[1]);
                mma_f16(oacc[2*j2+1], pa, vh[2], vh[3]);
            }
        }
    }

    // ---- epilogue ----
    lr0 += __shfl_xor_sync(0xffffffffu, lr0, 1);
    lr0 += __shfl_xor_sync(0xffffffffu, lr0, 2);
    lr1 += __shfl_xor_sync(0xffffffffu, lr1, 1);
    lr1 += __shfl_xor_sync(0xffffffffu, lr1, 2);
    const float qm0 = q_mask[(size_t)b * 2048 + qrow0];
    const float qm1 = q_mask[(size_t)b * 2048 + qrow0 + 8];
    const float inv0 = (lr0 > 0.f) ? qm0 / lr0 : 0.f;
    const float inv1 = (lr1 > 0.f) ? qm1 / lr1 : 0.f;
    float* o0 = out + (size_t)(b * 2048 + qrow0) * ODIM + h * 64;
    float* o1 = o0 + (size_t)8 * ODIM;
    #pragma unroll
    for (int j = 0; j < 8; j++) {
        *(float2*)(o0 + j * 8 + 2 * t) = make_float2(oacc[j][0] * inv0, oacc[j][1] * inv0);
        *(float2*)(o1 + j * 8 + 2 * t) = make_float2(oacc[j][2] * inv1, oacc[j][3] * inv1);
    }
}

// ---------------- degenerate rows (q >= last valid key): exact tie-average ----------------
__global__ void fallback_k(const float* __restrict__ v_mask, const float* __restrict__ q_mask,
                           float* __restrict__ out, const __half* __restrict__ Vw)
{
    const int h = blockIdx.x, b = blockIdx.y, d = threadIdx.x;  // 64 threads
    __shared__ int s_kmax, s_cnt;
    const float* vm = v_mask + (size_t)b * 2048;
    if (d == 0) {
        int km = 0, c = 0;
        for (int k2 = 0; k2 < 2048; k2++) if (vm[k2] != 0.f) { km = k2; c++; }
        s_kmax = km; s_cnt = c;
    }
    const __half* vh = Vw + (size_t)(b * 2048) * ODIM + h * 64 + d;
    float tm = 0.f;
    for (int k2 = 0; k2 < 2048; k2++)
        if (vm[k2] != 0.f) tm += __half2float(vh[(size_t)k2 * ODIM]);
    __syncthreads();
    const int kmax = s_kmax, cnt = s_cnt;
    float suf = 0.f;
    for (int k2 = 2047; k2 >= kmax; k2--) {
        const float qm = q_mask[(size_t)b * 2048 + k2];
        const int den = cnt + (2047 - k2);
        out[((size_t)(b * 2048 + k2)) * ODIM + h * 64 + d] =
            (den > 0) ? qm * (tm + suf) / (float)den : 0.f;
        suf += __half2float(vh[(size_t)k2 * ODIM]);
    }
}

// ---------------- launch ----------------
extern "C" void kernel_launch(void* const* d_in, const int* in_sizes, int n_in,
                              void* d_out, int out_size)
{
    const float* q     = (const float*)d_in[0];
    const float* k     = (const float*)d_in[1];
    const float* v     = (const float*)d_in[2];
    const float* vmask = (const float*)d_in[3];
    const float* qmask = (const float*)d_in[4];
    const float* Wq    = (const float*)d_in[5];
    const float* Wk    = (const float*)d_in[6];
    const float* Wv    = (const float*)d_in[7];
    float* out = (float*)d_out;

    __half *x16, *w16, *p16;
    cudaGetSymbolAddress((void**)&x16, g_x);
    cudaGetSymbolAddress((void**)&w16, g_w);
    cudaGetSymbolAddress((void**)&p16, g_p);

    cudaFuncSetAttribute(proj_mma, cudaFuncAttributeMaxDynamicSharedMemorySize, PJ_SMEM);
    cudaFuncSetAttribute(attn_mma, cudaFuncAttributeMaxDynamicSharedMemorySize, AT_SMEM);

    conv3<<<12288, 256>>>(q, k, v, x16, XSZ / 4);                     // launch 0
    conv3<<<3072, 256>>>(Wq, Wk, Wv, w16, WSZ / 4);                   // launch 1
    proj_mma<<<dim3(8, 32, 3), 256, PJ_SMEM>>>(x16, w16, p16);        // launch 2
    attn_mma<<<dim3(16, 16, 2), 256, AT_SMEM>>>(vmask, qmask, out, p16);  // launch 3
    fallback_k<<<dim3(16, 2), 64>>>(vmask, qmask, out, p16 + 2*XSZ);
}

// round 10
// speedup vs baseline: 3.2037x; 1.5520x over previous
#include <cuda_runtime.h>
#include <cuda_fp16.h>
#include <cstdint>

#define ODIM 1024
#define XSZ  4194304
#define WSZ  1048576
#define KOFF XSZ
#define VOFF (2*XSZ)
#define PPITCH 80           // proj smem pitch: 32 fp16 = 64B + 16B pad
#define APITCH 144          // attn smem pitch: 64 fp16 = 128B + 16B pad
#define PJ_SMEM 61440       // 3 stages x (A 10240 + B 10240)
#define AT_STG  18432       // attn per-stage: K 9216 + V 9216
#define AT_SMEM 56320       // 3*18432 + vm 3*256 + pad

__device__ __align__(16) __half g_x[3*XSZ];   // fp16 q,k,v inputs
__device__ __align__(16) __half g_w[3*WSZ];   // fp16 weights
__device__ __align__(16) __half g_p[3*XSZ];   // fp16 projections qw,kw,vw

// ---------------- helpers ----------------
__device__ __forceinline__ uint32_t smem_u32(const void* p) {
    uint32_t a;
    asm("{ .reg .u64 t; cvta.to.shared.u64 t, %1; cvt.u32.u64 %0, t; }" : "=r"(a) : "l"(p));
    return a;
}
__device__ __forceinline__ uint32_t packh2(float e0, float e1) {  // e0 -> low half
    __half2 h = __floats2half2_rn(e0, e1);
    return *reinterpret_cast<uint32_t*>(&h);
}
__device__ __forceinline__ void ldsm4(uint32_t* r, uint32_t a) {
    asm volatile("ldmatrix.sync.aligned.m8n8.x4.shared.b16 {%0,%1,%2,%3}, [%4];"
                 : "=r"(r[0]), "=r"(r[1]), "=r"(r[2]), "=r"(r[3]) : "r"(a));
}
__device__ __forceinline__ void ldsm4t(uint32_t* r, uint32_t a) {
    asm volatile("ldmatrix.sync.aligned.m8n8.x4.trans.shared.b16 {%0,%1,%2,%3}, [%4];"
                 : "=r"(r[0]), "=r"(r[1]), "=r"(r[2]), "=r"(r[3]) : "r"(a));
}
__device__ __forceinline__ void mma_f16(float* d, const uint32_t* a, uint32_t b0, uint32_t b1) {
    asm volatile("mma.sync.aligned.m16n8k16.row.col.f32.f16.f16.f32 "
                 "{%0,%1,%2,%3}, {%4,%5,%6,%7}, {%8,%9}, {%0,%1,%2,%3};"
                 : "+f"(d[0]), "+f"(d[1]), "+f"(d[2]), "+f"(d[3])
                 : "r"(a[0]), "r"(a[1]), "r"(a[2]), "r"(a[3]), "r"(b0), "r"(b1));
}
#define CPA16(dst, src) asm volatile("cp.async.cg.shared.global [%0], [%1], 16;" :: "r"(dst), "l"(src) : "memory")
#define CPC()   asm volatile("cp.async.commit_group;" ::: "memory")
#define CPW(n)  asm volatile("cp.async.wait_group %0;" :: "n"(n) : "memory")

// ---------------- convert fp32 -> fp16 (3 tensors per launch) ----------------
__global__ void conv3(const float* __restrict__ s0, const float* __restrict__ s1,
                      const float* __restrict__ s2, __half* __restrict__ h, int n4each) {
    int i = blockIdx.x * blockDim.x + threadIdx.x;
    int a = i / n4each;
    if (a > 2) return;
    int j = i - a * n4each;
    const float* s = (a == 0) ? s0 : (a == 1) ? s1 : s2;
    float4 v = ((const float4*)s)[j];
    uint2 hh;
    hh.x = packh2(v.x, v.y);
    hh.y = packh2(v.z, v.w);
    ((uint2*)h)[(size_t)a * n4each + j] = hh;
}

// ---------------- projection (3 fused via grid.z): C=X@W^T, tile 128x128, BK=32, 3-stage ----------------
__global__ __launch_bounds__(256) void proj_mma(
    const __half* __restrict__ X_, const __half* __restrict__ W_, __half* __restrict__ P_)
{
    extern __shared__ __align__(16) char sm[];
    const uint32_t sb = smem_u32(sm);
    const int z = blockIdx.z;
    const __half* A_ = X_ + (size_t)z * XSZ;
    const __half* B_ = W_ + (size_t)z * WSZ;
    __half* C_ = P_ + (size_t)z * XSZ;
    const int tid = threadIdx.x, wr = tid >> 5, lane = tid & 31;
    const int n0 = blockIdx.x * 128, m0 = blockIdx.y * 128;
    const int g = lane >> 2, t = lane & 3;
    const int wm = wr >> 1, wn = wr & 1;
    const uint32_t rB  = ((lane >> 4) & 1) * 8 + (lane & 7);
    const uint32_t cBo = ((lane >> 3) & 1) * 16;
    float acc[2][8][4] = {};

    auto issue = [&](int kt) {
        if (kt < 32) {
            const uint32_t base = sb + (uint32_t)(kt % 3) * 20480;
            #pragma unroll
            for (int i = 0; i < 4; i++) {
                int idx = tid + 256 * i;
                int arr = idx >> 9, r = (idx >> 2) & 127, gc = idx & 3;
                size_t go = (size_t)((arr ? n0 : m0) + r) * ODIM + kt * 32 + gc * 8;
                CPA16(base + arr * 10240 + r * PPITCH + gc * 16, (arr ? B_ : A_) + go);
            }
        }
        CPC();
    };

    issue(0); issue(1);
    for (int kt = 0; kt < 32; kt++) {
        CPW(1);
        __syncthreads();
        issue(kt + 2);
        const uint32_t base = sb + (uint32_t)(kt % 3) * 20480;
        #pragma unroll
        for (int kc = 0; kc < 2; kc++) {
            uint32_t ah[2][4];
            #pragma unroll
            for (int mi = 0; mi < 2; mi++)
                ldsm4(ah[mi], base + (wm * 32 + mi * 16 + (lane & 15)) * PPITCH
                              + (lane >> 4) * 16 + kc * 32);
            #pragma unroll
            for (int nj = 0; nj < 4; nj++) {
                uint32_t bh[4];
                ldsm4(bh, base + 10240 + (wn * 64 + nj * 16 + rB) * PPITCH + cBo + kc * 32);
                #pragma unroll
                for (int mi = 0; mi < 2; mi++) {
                    mma_f16(acc[mi][2*nj],   ah[mi], bh[0], bh[1]);
                    mma_f16(acc[mi][2*nj+1], ah[mi], bh[2], bh[3]);
                }
            }
        }
    }
    #pragma unroll
    for (int mi = 0; mi < 2; mi++) {
        const int r0 = m0 + wm * 32 + mi * 16 + g, r1 = r0 + 8;
        #pragma unroll
        for (int nj = 0; nj < 8; nj++) {
            int col = n0 + wn * 64 + nj * 8 + 2 * t;
            *(uint32_t*)(C_ + (size_t)r0 * ODIM + col) = packh2(acc[mi][nj][0], acc[mi][nj][1]);
            *(uint32_t*)(C_ + (size_t)r1 * ODIM + col) = packh2(acc[mi][nj][2], acc[mi][nj][3]);
        }
    }
}

// ---------------- attention: 128 q-rows/CTA, 64-key tiles, 3-stage, causal skip ----------------
__global__ __launch_bounds__(256) void attn_mma(
    const float* __restrict__ v_mask, const float* __restrict__ q_mask,
    float* __restrict__ out, const __half* __restrict__ P_)
{
    extern __shared__ __align__(16) char sm[];
    const uint32_t sb = smem_u32(sm);
    const int tid = threadIdx.x, wr = tid >> 5, lane = tid & 31;
    const int qt = blockIdx.x, h = blockIdx.y, b = blockIdx.z;
    const int q0 = qt * 128;
    const int g = lane >> 2, t = lane & 3;

    const __half* Q_b = P_ + (size_t)(b * 2048 + q0) * ODIM + h * 64;
    const __half* K_b = P_ + KOFF + (size_t)(b * 2048) * ODIM + h * 64;
    const __half* V_b = P_ + VOFF + (size_t)(b * 2048) * ODIM + h * 64;
    const float* vm = v_mask + (size_t)b * 2048;

    // ---- stage Q through stage-0 K area (two 64-row passes), grab fragments ----
    uint32_t qA[4][4];
    #pragma unroll
    for (int p = 0; p < 2; p++) {
        if (p) __syncthreads();
        #pragma unroll
        for (int i = 0; i < 2; i++) {
            int idx = tid + 256 * i;
            int r = (idx >> 3) & 63, gc = idx & 7;
            *(uint4*)(sm + r * APITCH + gc * 16) =
                *(const uint4*)(Q_b + (size_t)(p * 64 + r) * ODIM + gc * 8);
        }
        __syncthreads();
        if ((wr >> 2) == p) {
            const uint32_t aOff = sb + ((wr & 3) * 16 + (lane & 15)) * APITCH + (lane >> 4) * 16;
            #pragma unroll
            for (int kc = 0; kc < 4; kc++) ldsm4(qA[kc], aOff + kc * 32);
        }
    }
    __syncthreads();

    float oacc[8][4] = {};
    float lr0 = 0.f, lr1 = 0.f;
    const int qrow0 = q0 + wr * 16 + g;
    const uint32_t rB  = ((lane >> 4) & 1) * 8 + (lane & 7);
    const uint32_t cBo = ((lane >> 3) & 1) * 16;

    auto issue = [&](int kt2) {
        if (kt2 < 32) {
            const int st = kt2 % 3;
            const int k0 = kt2 * 64;
            const uint32_t bKs = sb + (uint32_t)st * AT_STG;
            #pragma unroll
            for (int i = 0; i < 4; i++) {
                int idx = tid + 256 * i;
                int arr = idx >> 9, r = (idx >> 3) & 63, gc = idx & 7;
                size_t go = (size_t)(k0 + r) * ODIM + gc * 8;
                CPA16(bKs + arr * 9216 + r * APITCH + gc * 16, (arr ? V_b : K_b) + go);
            }
            if (tid < 16) CPA16(sb + 3 * AT_STG + st * 256 + tid * 16, vm + k0 + tid * 4);
        }
        CPC();
    };

    const int start = 2 * qt;
    issue(start); issue(start + 1);
    for (int kt2 = start; kt2 < 32; kt2++) {
        const int st = kt2 % 3;
        const int k0 = kt2 * 64;
        CPW(1);
        __syncthreads();
        issue(kt2 + 2);
        const uint32_t bKs = sb + (uint32_t)st * AT_STG;
        const uint32_t bVs = bKs + 9216;
        const float* svm = (const float*)(sm + 3 * AT_STG + st * 256);
        const bool boundary = (kt2 < start + 2);   // only these tiles can hit kg<=qr

        #pragma unroll
        for (int jp = 0; jp < 4; jp++) {
            float s8[8] = {};
            #pragma unroll
            for (int kc = 0; kc < 4; kc++) {
                uint32_t bh[4];
                ldsm4(bh, bKs + (jp * 16 + rB) * APITCH + cBo + kc * 32);
                mma_f16(s8 + 0, qA[kc], bh[0], bh[1]);
                mma_f16(s8 + 4, qA[kc], bh[2], bh[3]);
            }
            float p[8];
            const int cb = jp * 16 + 2 * t;
            const float m0 = svm[cb], m1 = svm[cb + 1], m2 = svm[cb + 8], m3 = svm[cb + 9];
            if (boundary) {
                #pragma unroll
                for (int e = 0; e < 8; e++) {
                    int tile = e >> 2, c = e & 3;
                    int colL = cb + tile * 8 + (c & 1);
                    int kg = k0 + colL;
                    int qr = (c >= 2) ? qrow0 + 8 : qrow0;
                    float mv = (e < 4) ? ((e & 1) ? m1 : m0) : ((e & 1) ? m3 : m2);
                    p[e] = (kg <= qr) ? 0.f : __expf(s8[e] * 0.125f) * mv;
                }
            } else {
                p[0] = __expf(s8[0] * 0.125f) * m0;
                p[1] = __expf(s8[1] * 0.125f) * m1;
                p[2] = __expf(s8[2] * 0.125f) * m0;
                p[3] = __expf(s8[3] * 0.125f) * m1;
                p[4] = __expf(s8[4] * 0.125f) * m2;
                p[5] = __expf(s8[5] * 0.125f) * m3;
                p[6] = __expf(s8[6] * 0.125f) * m2;
                p[7] = __expf(s8[7] * 0.125f) * m3;
            }
            lr0 += p[0] + p[1] + p[4] + p[5];
            lr1 += p[2] + p[3] + p[6] + p[7];
            uint32_t pa[4];
            pa[0] = packh2(p[0], p[1]);  pa[1] = packh2(p[2], p[3]);
            pa[2] = packh2(p[4], p[5]);  pa[3] = packh2(p[6], p[7]);
            #pragma unroll
            for (int j2 = 0; j2 < 4; j2++) {
                uint32_t vh[4];
                ldsm4t(vh, bVs + (jp * 16 + (lane & 15)) * APITCH + (j2 * 2 + (lane >> 4)) * 16);
                mma_f16(oacc[2*j2],   pa, vh[0], vh[1]);
                mma_f16(oacc[2*j2+1], pa, vh[2], vh[3]);
            }
        }
    }

    // ---- epilogue ----
    lr0 += __shfl_xor_sync(0xffffffffu, lr0, 1);
    lr0 += __shfl_xor_sync(0xffffffffu, lr0, 2);
    lr1 += __shfl_xor_sync(0xffffffffu, lr1, 1);
    lr1 += __shfl_xor_sync(0xffffffffu, lr1, 2);
    const float qm0 = q_mask[(size_t)b * 2048 + qrow0];
    const float qm1 = q_mask[(size_t)b * 2048 + qrow0 + 8];
    const float inv0 = (lr0 > 0.f) ? qm0 / lr0 : 0.f;
    const float inv1 = (lr1 > 0.f) ? qm1 / lr1 : 0.f;
    float* o0 = out + (size_t)(b * 2048 + qrow0) * ODIM + h * 64;
    float* o1 = o0 + (size_t)8 * ODIM;
    #pragma unroll
    for (int j = 0; j < 8; j++) {
        *(float2*)(o0 + j * 8 + 2 * t) = make_float2(oacc[j][0] * inv0, oacc[j][1] * inv0);
        *(float2*)(o1 + j * 8 + 2 * t) = make_float2(oacc[j][2] * inv1, oacc[j][3] * inv1);
    }
}

// ---------------- degenerate rows (q >= last valid key): exact tie-average, parallel ----------------
__global__ __launch_bounds__(512) void fallback_k(
    const float* __restrict__ v_mask, const float* __restrict__ q_mask,
    float* __restrict__ out, const __half* __restrict__ Vw)
{
    __shared__ int smax[512], scnt[512];
    __shared__ float spart[512];
    const int h = blockIdx.x, b = blockIdx.y, tid = threadIdx.x;
    const float* vm = v_mask + (size_t)b * 2048;

    // phase A: kmax & cnt (parallel scan + tree reduce)
    int km = -1, c = 0;
    for (int k2 = tid; k2 < 2048; k2 += 512)
        if (vm[k2] != 0.f) { if (k2 > km) km = k2; c++; }
    smax[tid] = km; scnt[tid] = c;
    __syncthreads();
    for (int s = 256; s > 0; s >>= 1) {
        if (tid < s) {
            if (smax[tid + s] > smax[tid]) smax[tid] = smax[tid + s];
            scnt[tid] += scnt[tid + s];
        }
        __syncthreads();
    }
    const int kmax = (smax[0] < 0) ? 0 : smax[0];
    const int cnt = scnt[0];

    // phase B: tm[d] = sum over valid keys of V[k][d], 8 k-slices per d
    const int d = tid & 63, sl = tid >> 6;           // 8 slices x 256 keys
    const __half* vh = Vw + (size_t)(b * 2048) * ODIM + h * 64 + d;
    float part = 0.f;
    for (int k2 = sl * 256; k2 < sl * 256 + 256; k2++)
        if (vm[k2] != 0.f) part += __half2float(vh[(size_t)k2 * ODIM]);
    spart[tid] = part;
    __syncthreads();

    // phase C: 64 threads finish (serial suffix, typically ~8 iterations)
    if (tid < 64) {
        float tm = 0.f;
        #pragma unroll
        for (int s = 0; s < 8; s++) tm += spart[s * 64 + d];
        float suf = 0.f;
        for (int k2 = 2047; k2 >= kmax; k2--) {
            const float qm = q_mask[(size_t)b * 2048 + k2];
            const int den = cnt + (2047 - k2);
            out[((size_t)(b * 2048 + k2)) * ODIM + h * 64 + d] =
                (den > 0) ? qm * (tm + suf) / (float)den : 0.f;
            suf += __half2float(vh[(size_t)k2 * ODIM]);
        }
    }
}

// ---------------- launch ----------------
extern "C" void kernel_launch(void* const* d_in, const int* in_sizes, int n_in,
                              void* d_out, int out_size)
{
    const float* q     = (const float*)d_in[0];
    const float* k     = (const float*)d_in[1];
    const float* v     = (const float*)d_in[2];
    const float* vmask = (const float*)d_in[3];
    const float* qmask = (const float*)d_in[4];
    const float* Wq    = (const float*)d_in[5];
    const float* Wk    = (const float*)d_in[6];
    const float* Wv    = (const float*)d_in[7];
    float* out = (float*)d_out;

    __half *x16, *w16, *p16;
    cudaGetSymbolAddress((void**)&x16, g_x);
    cudaGetSymbolAddress((void**)&w16, g_w);
    cudaGetSymbolAddress((void**)&p16, g_p);

    cudaFuncSetAttribute(proj_mma, cudaFuncAttributeMaxDynamicSharedMemorySize, PJ_SMEM);
    cudaFuncSetAttribute(attn_mma, cudaFuncAttributeMaxDynamicSharedMemorySize, AT_SMEM);

    conv3<<<12288, 256>>>(q, k, v, x16, XSZ / 4);
    conv3<<<3072, 256>>>(Wq, Wk, Wv, w16, WSZ / 4);
    proj_mma<<<dim3(8, 32, 3), 256, PJ_SMEM>>>(x16, w16, p16);
    attn_mma<<<dim3(16, 16, 2), 256, AT_SMEM>>>(vmask, qmask, out, p16);
    fallback_k<<<dim3(16, 2), 512>>>(vmask, qmask, out, p16 + 2*XSZ);
}